// round 12
// baseline (speedup 1.0000x reference)
#include <cuda_runtime.h>
#include <cuda_fp16.h>

#define NN 100000
#define IN_DIM 128
#define HID 32
#define ODIM 12
#define MAXE 3400000
#define SCAN_EPB 4096                              // elements per scanA block
#define NB_SCAN ((NN + SCAN_EPB - 1) / SCAN_EPB)   // 25

// Scratch (device globals; no allocation allowed). g_cnt relies on static
// zero-init for the first call; scanC re-zeroes it for every subsequent call.
__device__ __align__(128) __half g_h1h[NN * HID];    // feat @ W1  (fp16 at rest)
__device__ __align__(128) __half g_xh[NN * HID];     // layer-1 activations (fp16)
__device__ __align__(128) __half g_h2h[NN * ODIM];   // x @ W2     (fp16 at rest)
__device__ __align__(128) int    g_ssrc[MAXE];       // src sorted by dst
__device__ __align__(16) int g_cnt[NN];
__device__ __align__(16) int g_scanA[NN];            // exclusive-within-block
__device__ int g_rowstart[NN + 1];
__device__ int g_cursor[NN];
__device__ int g_bsum[32];

#define ADD_F32X2(out, a, b) \
    asm("add.rn.f32x2 %0, %1, %2;" : "=l"(out) : "l"(a), "l"(b))
#define FMA_F32X2(out, a, b, c) \
    asm("fma.rn.f32x2 %0, %1, %2, %3;" : "=l"(out) : "l"(a), "l"(b), "l"(c))

__device__ __forceinline__ unsigned long long pack_f2(float2 f) {
    unsigned long long t;
    asm("mov.b64 %0, {%1, %2};" : "=l"(t) : "f"(f.x), "f"(f.y));
    return t;
}
__device__ __forceinline__ float2 unpack_f2(unsigned long long u) {
    float2 f;
    asm("mov.b64 {%0, %1}, %2;" : "=f"(f.x), "=f"(f.y) : "l"(u));
    return f;
}

// ---------------------------------------------------------------------------
// CSR build: degree histogram (4 edges/thread). Assumes g_cnt is zero
// (static init on call 1; scanC zeroes it at the end of every call).
__global__ void hist_kernel(const int4* __restrict__ dst4, int E4, int E,
                            const int* __restrict__ dst) {
    int i = blockIdx.x * blockDim.x + threadIdx.x;
    if (i < E4) {
        int4 d = dst4[i];
        atomicAdd(&g_cnt[d.x], 1);
        atomicAdd(&g_cnt[d.y], 1);
        atomicAdd(&g_cnt[d.z], 1);
        atomicAdd(&g_cnt[d.w], 1);
    }
    int tail = E4 * 4 + i;
    if (i < (E - E4 * 4)) atomicAdd(&g_cnt[dst[tail]], 1);
}

// Scan stage A: 4 elems/thread (int4), EXCLUSIVE-within-block output.
__global__ __launch_bounds__(1024) void scanA_kernel() {
    __shared__ int wsum[32];
    int tid = threadIdx.x, lane = tid & 31, wid = tid >> 5;
    int i4 = blockIdx.x * 1024 + tid;
    const int N4 = NN / 4;  // 25000
    int4 c = (i4 < N4) ? ((const int4*)g_cnt)[i4] : make_int4(0, 0, 0, 0);
    int l0 = c.x;
    int l1 = l0 + c.y;
    int l2 = l1 + c.z;
    int l3 = l2 + c.w;
    int x = l3;
#pragma unroll
    for (int o = 1; o < 32; o <<= 1) {
        int t = __shfl_up_sync(0xffffffffu, x, o);
        if (lane >= o) x += t;
    }
    if (lane == 31) wsum[wid] = x;
    __syncthreads();
    if (wid == 0) {
        int s = wsum[lane];
#pragma unroll
        for (int o = 1; o < 32; o <<= 1) {
            int t = __shfl_up_sync(0xffffffffu, s, o);
            if (lane >= o) s += t;
        }
        wsum[lane] = s;
    }
    __syncthreads();
    int add = (wid > 0 ? wsum[wid - 1] : 0) + (x - l3);  // exclusive of this thread
    if (i4 < N4) {
        int4 o;
        o.x = add; o.y = add + l0; o.z = add + l1; o.w = add + l2;
        ((int4*)g_scanA)[i4] = o;
    }
    if (tid == 1023) g_bsum[blockIdx.x] = wsum[31];
}

// Scan stage C (scanB inlined): every block shfl-scans the 25 block sums,
// then computes rowstart/cursor; also re-zeroes g_cnt for the next call.
__global__ __launch_bounds__(256) void scanC_kernel(int E) {
    __shared__ int boff[32];
    int tid = threadIdx.x;
    if (tid < 32) {
        int v = (tid < NB_SCAN) ? g_bsum[tid] : 0;
        int x = v;
#pragma unroll
        for (int o = 1; o < 32; o <<= 1) {
            int t = __shfl_up_sync(0xffffffffu, x, o);
            if (tid >= o) x += t;
        }
        boff[tid] = x - v;  // exclusive
    }
    __syncthreads();
    int n = blockIdx.x * 256 + tid;
    if (n < NN) {
        int rs = boff[n >> 12] + g_scanA[n];   // SCAN_EPB = 4096 = 1<<12
        g_rowstart[n] = rs;
        g_cursor[n] = rs;
        g_cnt[n] = 0;                          // clean for next call's hist
    }
    if (n == 0) g_rowstart[NN] = E;
}

// ---------------------------------------------------------------------------
// Permute: bucket src indices by dst (4 edges/thread)
__global__ void permute_kernel(const int4* __restrict__ src4,
                               const int4* __restrict__ dst4, int E4, int E,
                               const int* __restrict__ src,
                               const int* __restrict__ dst) {
    int i = blockIdx.x * blockDim.x + threadIdx.x;
    if (i < E4) {
        int4 s = src4[i];
        int4 d = dst4[i];
        g_ssrc[atomicAdd(&g_cursor[d.x], 1)] = s.x;
        g_ssrc[atomicAdd(&g_cursor[d.y], 1)] = s.y;
        g_ssrc[atomicAdd(&g_cursor[d.z], 1)] = s.z;
        g_ssrc[atomicAdd(&g_cursor[d.w], 1)] = s.w;
    }
    int tail = E4 * 4 + i;
    if (i < (E - E4 * 4))
        g_ssrc[atomicAdd(&g_cursor[dst[tail]], 1)] = src[tail];
}

// ---------------------------------------------------------------------------
// h1 = feat @ W1, stored fp16. Packed fma.rn.f32x2 mainloop, fully unrolled.
// __launch_bounds__(256, 2) lifts the reg cap to 128 so ptxas can pipeline
// the LDS stream against the FFMA2 chain (prior 64-reg cap exposed LDS lat).
__global__ __launch_bounds__(256, 2) void gemm1_kernel(const float4* __restrict__ feat4,
                                                       const float* __restrict__ W1) {
    __shared__ __align__(16) float fs[64][128];                 // 32 KB
    __shared__ __align__(16) float2 Wp[IN_DIM / 2][HID];        // 16 KB
    int tid = threadIdx.x;
    int base = blockIdx.x * 64;

    // Wp[k2][j] = (W1[2k2][j], W1[2k2+1][j])
    for (int i = tid; i < (IN_DIM / 2) * HID; i += 256) {
        int k2 = i >> 5, j = i & 31;
        Wp[k2][j] = make_float2(W1[(2 * k2) * HID + j],
                                W1[(2 * k2 + 1) * HID + j]);
    }

    float4* fs4 = (float4*)fs;
    for (int i = tid; i < 64 * 32; i += 256) {
        int row = i >> 5, c = i & 31;
        int g = base + row;
        fs4[i] = (g < NN) ? feat4[(long long)g * 32 + c]
                          : make_float4(0.f, 0.f, 0.f, 0.f);
    }
    __syncthreads();

    int warp = tid >> 5, lane = tid & 31;
    int r0 = warp * 8;
    unsigned long long acc[8];
#pragma unroll
    for (int r = 0; r < 8; r++) acc[r] = 0ull;

#pragma unroll
    for (int k = 0; k < IN_DIM; k += 4) {
        unsigned long long wA = pack_f2(Wp[k >> 1][lane]);        // (w[k],   w[k+1])
        unsigned long long wB = pack_f2(Wp[(k >> 1) + 1][lane]);  // (w[k+2], w[k+3])
#pragma unroll
        for (int r = 0; r < 8; r++) {
            ulonglong2 f = *(const ulonglong2*)&fs[r0 + r][k];    // one LDS.128
            FMA_F32X2(acc[r], f.x, wA, acc[r]);
            FMA_F32X2(acc[r], f.y, wB, acc[r]);
        }
    }
#pragma unroll
    for (int r = 0; r < 8; r++) {
        int g = base + r0 + r;
        if (g < NN) {
            float2 p = unpack_f2(acc[r]);
            g_h1h[(long long)g * HID + lane] = __float2half_rn(p.x + p.y);
        }
    }
}

// ---------------------------------------------------------------------------
// Gather 1 + finalize. Warp per node. Lane -> (edge-slot lane>>2, colgrp lane&3).
// Index prefetch + packed f32x2 accumulation. Output x stored fp16.
__global__ __launch_bounds__(256) void gather1_kernel(const float4* __restrict__ b1v) {
    int w = (blockIdx.x * 256 + threadIdx.x) >> 5;
    int lane = threadIdx.x & 31;
    if (w >= NN) return;
    int e0 = __ldg(&g_rowstart[w]);
    int e1 = __ldg(&g_rowstart[w + 1]);

    int slot = lane >> 2;     // 0..7 : edge within group of 8
    int cg   = lane & 3;      // 0..3 : which float4 (8 halves) of the 64B row
    const float4* h4 = (const float4*)g_h1h;

    unsigned long long A0 = 0ull, A1 = 0ull, A2 = 0ull, A3 = 0ull;

    int idx = e0 + slot;
    bool val = idx < e1;
    int s = val ? __ldg(&g_ssrc[idx]) : 0;
#pragma unroll 4
    for (int base = e0; base < e1; base += 8) {
        int nidx = base + 8 + slot;
        bool nval = nidx < e1;
        int ns = nval ? __ldg(&g_ssrc[nidx]) : 0;   // prefetch next group
        float4 v = __ldg(&h4[s * 4 + cg]);
        if (val) {
            const __half2* hp = (const __half2*)&v;
            ADD_F32X2(A0, A0, pack_f2(__half22float2(hp[0])));
            ADD_F32X2(A1, A1, pack_f2(__half22float2(hp[1])));
            ADD_F32X2(A2, A2, pack_f2(__half22float2(hp[2])));
            ADD_F32X2(A3, A3, pack_f2(__half22float2(hp[3])));
        }
        s = ns; val = nval;
    }
    float2 f0 = unpack_f2(A0), f1 = unpack_f2(A1);
    float2 f2 = unpack_f2(A2), f3 = unpack_f2(A3);
    float a0 = f0.x, a1 = f0.y, a2 = f1.x, a3 = f1.y;
    float a4 = f2.x, a5 = f2.y, a6 = f3.x, a7 = f3.y;
    // reduce over edge-slots (lane bits 2,3,4)
#pragma unroll
    for (int ofs = 4; ofs <= 16; ofs <<= 1) {
        a0 += __shfl_xor_sync(0xffffffffu, a0, ofs);
        a1 += __shfl_xor_sync(0xffffffffu, a1, ofs);
        a2 += __shfl_xor_sync(0xffffffffu, a2, ofs);
        a3 += __shfl_xor_sync(0xffffffffu, a3, ofs);
        a4 += __shfl_xor_sync(0xffffffffu, a4, ofs);
        a5 += __shfl_xor_sync(0xffffffffu, a5, ofs);
        a6 += __shfl_xor_sync(0xffffffffu, a6, ofs);
        a7 += __shfl_xor_sync(0xffffffffu, a7, ofs);
    }
    if (lane < 4) {   // lane == cg, slot 0: owns columns cg*8 .. cg*8+7
        float invd = 1.0f / fmaxf((float)(e1 - e0), 1.0f);
        float4 bA = __ldg(&b1v[lane * 2 + 0]);
        float4 bB = __ldg(&b1v[lane * 2 + 1]);
        uint4 u;
        ((__half2*)&u)[0] = __floats2half2_rn(fmaxf(a0 * invd + bA.x, 0.f),
                                              fmaxf(a1 * invd + bA.y, 0.f));
        ((__half2*)&u)[1] = __floats2half2_rn(fmaxf(a2 * invd + bA.z, 0.f),
                                              fmaxf(a3 * invd + bA.w, 0.f));
        ((__half2*)&u)[2] = __floats2half2_rn(fmaxf(a4 * invd + bB.x, 0.f),
                                              fmaxf(a5 * invd + bB.y, 0.f));
        ((__half2*)&u)[3] = __floats2half2_rn(fmaxf(a6 * invd + bB.z, 0.f),
                                              fmaxf(a7 * invd + bB.w, 0.f));
        ((uint4*)g_xh)[w * 4 + lane] = u;   // 8 halves: cols cg*8..cg*8+7
    }
}

// ---------------------------------------------------------------------------
// h2 = x(fp16) @ W2   [NN,32] x [32,12], stored fp16 (24B rows)
__global__ __launch_bounds__(256) void gemm2_kernel(const float* __restrict__ W2) {
    __shared__ float W2s[HID * ODIM];
    int tid = threadIdx.x;
    for (int i = tid; i < HID * ODIM; i += 256) W2s[i] = W2[i];
    __syncthreads();

    int n = blockIdx.x * blockDim.x + tid;
    if (n >= NN) return;

    float acc[ODIM];
#pragma unroll
    for (int j = 0; j < ODIM; j++) acc[j] = 0.f;

    const uint4* x4 = (const uint4*)g_xh + (long long)n * 4;  // 4 x uint4 = 32 halves
#pragma unroll
    for (int q = 0; q < 4; q++) {
        uint4 u = x4[q];
        const __half2* hp = (const __half2*)&u;
#pragma unroll
        for (int p = 0; p < 4; p++) {
            float2 xv = __half22float2(hp[p]);
            int c = q * 8 + p * 2;
#pragma unroll
            for (int j = 0; j < ODIM; j++) {
                acc[j] += xv.x * W2s[(c + 0) * ODIM + j]
                        + xv.y * W2s[(c + 1) * ODIM + j];
            }
        }
    }
    uint2 u0, u1, u2;
    ((__half2*)&u0)[0] = __floats2half2_rn(acc[0], acc[1]);
    ((__half2*)&u0)[1] = __floats2half2_rn(acc[2], acc[3]);
    ((__half2*)&u1)[0] = __floats2half2_rn(acc[4], acc[5]);
    ((__half2*)&u1)[1] = __floats2half2_rn(acc[6], acc[7]);
    ((__half2*)&u2)[0] = __floats2half2_rn(acc[8], acc[9]);
    ((__half2*)&u2)[1] = __floats2half2_rn(acc[10], acc[11]);
    uint2* o = (uint2*)(g_h2h + (long long)n * ODIM);
    o[0] = u0; o[1] = u1; o[2] = u2;
}

// ---------------------------------------------------------------------------
// Gather 2 + finalize. Warp per node. fp16 rows (24B = 3x uint2).
// Index prefetch + packed f32x2 accumulation; 8 edges per LDG.64 warp-instr.
__global__ __launch_bounds__(256) void gather2_kernel(const float4* __restrict__ b2v,
                                                      float4* __restrict__ out4) {
    int w = (blockIdx.x * 256 + threadIdx.x) >> 5;
    int lane = threadIdx.x & 31;
    if (w >= NN) return;
    int e0 = __ldg(&g_rowstart[w]);
    int e1 = __ldg(&g_rowstart[w + 1]);

    int slot = lane >> 2;     // 0..7
    int cg   = lane & 3;      // 0..3 (3 idle)
    bool cact = cg < 3;
    const uint2* hp = (const uint2*)g_h2h;
    int coff = cact ? cg : 0;

    unsigned long long A0 = 0ull, A1 = 0ull;

    int idx = e0 + slot;
    bool val = idx < e1;
    int s = val ? __ldg(&g_ssrc[idx]) : 0;
#pragma unroll 4
    for (int base = e0; base < e1; base += 8) {
        int nidx = base + 8 + slot;
        bool nval = nidx < e1;
        int ns = nval ? __ldg(&g_ssrc[nidx]) : 0;
        uint2 d = __ldg(&hp[s * 3 + coff]);
        if (val && cact) {
            ADD_F32X2(A0, A0, pack_f2(__half22float2(*(const __half2*)&d.x)));
            ADD_F32X2(A1, A1, pack_f2(__half22float2(*(const __half2*)&d.y)));
        }
        s = ns; val = nval;
    }
    float2 f0 = unpack_f2(A0), f1 = unpack_f2(A1);
    float a0 = f0.x, a1 = f0.y, a2 = f1.x, a3 = f1.y;
#pragma unroll
    for (int ofs = 4; ofs <= 16; ofs <<= 1) {
        a0 += __shfl_xor_sync(0xffffffffu, a0, ofs);
        a1 += __shfl_xor_sync(0xffffffffu, a1, ofs);
        a2 += __shfl_xor_sync(0xffffffffu, a2, ofs);
        a3 += __shfl_xor_sync(0xffffffffu, a3, ofs);
    }
    if (lane < 3) {   // lane == cg: owns columns cg*4 .. cg*4+3
        float invd = 1.0f / fmaxf((float)(e1 - e0), 1.0f);
        float4 b = __ldg(&b2v[lane]);
        float4 o;
        o.x = fmaxf(a0 * invd + b.x, 0.f);
        o.y = fmaxf(a1 * invd + b.y, 0.f);
        o.z = fmaxf(a2 * invd + b.z, 0.f);
        o.w = fmaxf(a3 * invd + b.w, 0.f);
        out4[w * 3 + lane] = o;
    }
}

// ---------------------------------------------------------------------------
extern "C" void kernel_launch(void* const* d_in, const int* in_sizes, int n_in,
                              void* d_out, int out_size) {
    const float* feat = (const float*)d_in[0];  // [NN,128]
    const int*   src  = (const int*)d_in[1];    // [E]
    const int*   dst  = (const int*)d_in[2];    // [E]
    const float* W1   = (const float*)d_in[3];  // [128,32]
    const float* b1   = (const float*)d_in[4];  // [32]
    const float* W2   = (const float*)d_in[5];  // [32,12]
    const float* b2   = (const float*)d_in[6];  // [12]
    float* out = (float*)d_out;                 // [NN,12]

    int E = in_sizes[1];
    int E4 = E / 4;

    // Launch index 3 = permute (ncu captures idx 3 -> E-scale atomic profile)
    hist_kernel<<<(E4 + 255) / 256, 256>>>((const int4*)dst, E4, E, dst);      // 0
    scanA_kernel<<<NB_SCAN, 1024>>>();                                          // 1
    scanC_kernel<<<(NN + 255) / 256, 256>>>(E);                                 // 2
    permute_kernel<<<(E4 + 255) / 256, 256>>>((const int4*)src, (const int4*)dst,
                                              E4, E, src, dst);                 // 3
    gemm1_kernel<<<(NN + 63) / 64, 256>>>((const float4*)feat, W1);             // 4
    gather1_kernel<<<(NN * 32 + 255) / 256, 256>>>((const float4*)b1);          // 5
    gemm2_kernel<<<(NN + 255) / 256, 256>>>(W2);                                // 6
    gather2_kernel<<<(NN * 32 + 255) / 256, 256>>>((const float4*)b2,
                                                   (float4*)out);               // 7
}

// round 14
// speedup vs baseline: 1.4173x; 1.4173x over previous
#include <cuda_runtime.h>
#include <cuda_fp16.h>

#define NN 100000
#define IN_DIM 128
#define HID 32
#define ODIM 12
#define MAXE 3400000
#define SCAN_EPB 4096                              // elements per scanA block
#define NB_SCAN ((NN + SCAN_EPB - 1) / SCAN_EPB)   // 25

// Scratch (device globals; no allocation allowed). g_cnt relies on static
// zero-init for the first call; scanC re-zeroes it for every subsequent call.
__device__ __align__(128) __half g_h1h[NN * HID];    // feat @ W1  (fp16 at rest)
__device__ __align__(128) __half g_xh[NN * HID];     // layer-1 activations (fp16)
__device__ __align__(128) __half g_h2h[NN * ODIM];   // x @ W2     (fp16 at rest)
__device__ __align__(128) int    g_ssrc[MAXE];       // src sorted by dst
__device__ __align__(16) int g_cnt[NN];
__device__ __align__(16) int g_scanA[NN];            // exclusive-within-block
__device__ int g_rowstart[NN + 1];
__device__ int g_cursor[NN];
__device__ int g_bsum[32];

#define ADD_F32X2(out, a, b) \
    asm("add.rn.f32x2 %0, %1, %2;" : "=l"(out) : "l"(a), "l"(b))
#define FMA_F32X2(out, a, b, c) \
    asm("fma.rn.f32x2 %0, %1, %2, %3;" : "=l"(out) : "l"(a), "l"(b), "l"(c))

__device__ __forceinline__ unsigned long long pack_f2(float2 f) {
    unsigned long long t;
    asm("mov.b64 %0, {%1, %2};" : "=l"(t) : "f"(f.x), "f"(f.y));
    return t;
}
__device__ __forceinline__ float2 unpack_f2(unsigned long long u) {
    float2 f;
    asm("mov.b64 {%0, %1}, %2;" : "=f"(f.x), "=f"(f.y) : "l"(u));
    return f;
}

// ---------------------------------------------------------------------------
// CSR build: degree histogram, 8 edges/thread for MLP (atomics independent).
__global__ void hist_kernel(const int4* __restrict__ dst4, int E8, int E,
                            const int* __restrict__ dst) {
    int i = blockIdx.x * blockDim.x + threadIdx.x;
    if (i < E8) {
        int4 d0 = dst4[2 * i];
        int4 d1 = dst4[2 * i + 1];
        atomicAdd(&g_cnt[d0.x], 1);
        atomicAdd(&g_cnt[d0.y], 1);
        atomicAdd(&g_cnt[d0.z], 1);
        atomicAdd(&g_cnt[d0.w], 1);
        atomicAdd(&g_cnt[d1.x], 1);
        atomicAdd(&g_cnt[d1.y], 1);
        atomicAdd(&g_cnt[d1.z], 1);
        atomicAdd(&g_cnt[d1.w], 1);
    }
    int tail = E8 * 8 + i;
    if (i < (E - E8 * 8)) atomicAdd(&g_cnt[dst[tail]], 1);
}

// Scan stage A: 4 elems/thread (int4), EXCLUSIVE-within-block output.
__global__ __launch_bounds__(1024) void scanA_kernel() {
    __shared__ int wsum[32];
    int tid = threadIdx.x, lane = tid & 31, wid = tid >> 5;
    int i4 = blockIdx.x * 1024 + tid;
    const int N4 = NN / 4;  // 25000
    int4 c = (i4 < N4) ? ((const int4*)g_cnt)[i4] : make_int4(0, 0, 0, 0);
    int l0 = c.x;
    int l1 = l0 + c.y;
    int l2 = l1 + c.z;
    int l3 = l2 + c.w;
    int x = l3;
#pragma unroll
    for (int o = 1; o < 32; o <<= 1) {
        int t = __shfl_up_sync(0xffffffffu, x, o);
        if (lane >= o) x += t;
    }
    if (lane == 31) wsum[wid] = x;
    __syncthreads();
    if (wid == 0) {
        int s = wsum[lane];
#pragma unroll
        for (int o = 1; o < 32; o <<= 1) {
            int t = __shfl_up_sync(0xffffffffu, s, o);
            if (lane >= o) s += t;
        }
        wsum[lane] = s;
    }
    __syncthreads();
    int add = (wid > 0 ? wsum[wid - 1] : 0) + (x - l3);  // exclusive of this thread
    if (i4 < N4) {
        int4 o;
        o.x = add; o.y = add + l0; o.z = add + l1; o.w = add + l2;
        ((int4*)g_scanA)[i4] = o;
    }
    if (tid == 1023) g_bsum[blockIdx.x] = wsum[31];
}

// Scan stage C (scanB inlined): every block shfl-scans the 25 block sums,
// then computes rowstart/cursor; also re-zeroes g_cnt for the next call.
__global__ __launch_bounds__(256) void scanC_kernel(int E) {
    __shared__ int boff[32];
    int tid = threadIdx.x;
    if (tid < 32) {
        int v = (tid < NB_SCAN) ? g_bsum[tid] : 0;
        int x = v;
#pragma unroll
        for (int o = 1; o < 32; o <<= 1) {
            int t = __shfl_up_sync(0xffffffffu, x, o);
            if (tid >= o) x += t;
        }
        boff[tid] = x - v;  // exclusive
    }
    __syncthreads();
    int n = blockIdx.x * 256 + tid;
    if (n < NN) {
        int rs = boff[n >> 12] + g_scanA[n];   // SCAN_EPB = 4096 = 1<<12
        g_rowstart[n] = rs;
        g_cursor[n] = rs;
        g_cnt[n] = 0;                          // clean for next call's hist
    }
    if (n == 0) g_rowstart[NN] = E;
}

// ---------------------------------------------------------------------------
// Permute: bucket src indices by dst. 8 edges/thread -> 8 independent
// ATOMG->STG chains per thread (kernel is stall-bound at issue=3.4%, so
// doubling MLP converts exposed atomic latency into overlap).
__global__ void permute_kernel(const int4* __restrict__ src4,
                               const int4* __restrict__ dst4, int E8, int E,
                               const int* __restrict__ src,
                               const int* __restrict__ dst) {
    int i = blockIdx.x * blockDim.x + threadIdx.x;
    if (i < E8) {
        int4 s0 = src4[2 * i],     s1 = src4[2 * i + 1];
        int4 d0 = dst4[2 * i],     d1 = dst4[2 * i + 1];
        int p0 = atomicAdd(&g_cursor[d0.x], 1);
        int p1 = atomicAdd(&g_cursor[d0.y], 1);
        int p2 = atomicAdd(&g_cursor[d0.z], 1);
        int p3 = atomicAdd(&g_cursor[d0.w], 1);
        int p4 = atomicAdd(&g_cursor[d1.x], 1);
        int p5 = atomicAdd(&g_cursor[d1.y], 1);
        int p6 = atomicAdd(&g_cursor[d1.z], 1);
        int p7 = atomicAdd(&g_cursor[d1.w], 1);
        g_ssrc[p0] = s0.x;
        g_ssrc[p1] = s0.y;
        g_ssrc[p2] = s0.z;
        g_ssrc[p3] = s0.w;
        g_ssrc[p4] = s1.x;
        g_ssrc[p5] = s1.y;
        g_ssrc[p6] = s1.z;
        g_ssrc[p7] = s1.w;
    }
    int tail = E8 * 8 + i;
    if (i < (E - E8 * 8))
        g_ssrc[atomicAdd(&g_cursor[dst[tail]], 1)] = src[tail];
}

// ---------------------------------------------------------------------------
// h1 = feat @ W1, stored fp16. Packed fma.rn.f32x2 mainloop (R10 config:
// default reg cap, unroll 4 — the (256,2)+full-unroll variant tanked occupancy).
__global__ __launch_bounds__(256) void gemm1_kernel(const float4* __restrict__ feat4,
                                                    const float* __restrict__ W1) {
    __shared__ __align__(16) float fs[64][128];                 // 32 KB
    __shared__ __align__(16) float2 Wp[IN_DIM / 2][HID];        // 16 KB
    int tid = threadIdx.x;
    int base = blockIdx.x * 64;

    // Wp[k2][j] = (W1[2k2][j], W1[2k2+1][j])
    for (int i = tid; i < (IN_DIM / 2) * HID; i += 256) {
        int k2 = i >> 5, j = i & 31;
        Wp[k2][j] = make_float2(W1[(2 * k2) * HID + j],
                                W1[(2 * k2 + 1) * HID + j]);
    }

    float4* fs4 = (float4*)fs;
    for (int i = tid; i < 64 * 32; i += 256) {
        int row = i >> 5, c = i & 31;
        int g = base + row;
        fs4[i] = (g < NN) ? feat4[(long long)g * 32 + c]
                          : make_float4(0.f, 0.f, 0.f, 0.f);
    }
    __syncthreads();

    int warp = tid >> 5, lane = tid & 31;
    int r0 = warp * 8;
    unsigned long long acc[8];
#pragma unroll
    for (int r = 0; r < 8; r++) acc[r] = 0ull;

#pragma unroll 4
    for (int k = 0; k < IN_DIM; k += 4) {
        unsigned long long wA = pack_f2(Wp[k >> 1][lane]);        // (w[k],   w[k+1])
        unsigned long long wB = pack_f2(Wp[(k >> 1) + 1][lane]);  // (w[k+2], w[k+3])
#pragma unroll
        for (int r = 0; r < 8; r++) {
            ulonglong2 f = *(const ulonglong2*)&fs[r0 + r][k];    // one LDS.128
            FMA_F32X2(acc[r], f.x, wA, acc[r]);
            FMA_F32X2(acc[r], f.y, wB, acc[r]);
        }
    }
#pragma unroll
    for (int r = 0; r < 8; r++) {
        int g = base + r0 + r;
        if (g < NN) {
            float2 p = unpack_f2(acc[r]);
            g_h1h[(long long)g * HID + lane] = __float2half_rn(p.x + p.y);
        }
    }
}

// ---------------------------------------------------------------------------
// Gather 1 + finalize. Warp per node. Lane -> (edge-slot lane>>2, colgrp lane&3).
// Index prefetch + packed f32x2 accumulation. Output x stored fp16.
__global__ __launch_bounds__(256) void gather1_kernel(const float4* __restrict__ b1v) {
    int w = (blockIdx.x * 256 + threadIdx.x) >> 5;
    int lane = threadIdx.x & 31;
    if (w >= NN) return;
    int e0 = __ldg(&g_rowstart[w]);
    int e1 = __ldg(&g_rowstart[w + 1]);

    int slot = lane >> 2;     // 0..7 : edge within group of 8
    int cg   = lane & 3;      // 0..3 : which float4 (8 halves) of the 64B row
    const float4* h4 = (const float4*)g_h1h;

    unsigned long long A0 = 0ull, A1 = 0ull, A2 = 0ull, A3 = 0ull;

    int idx = e0 + slot;
    bool val = idx < e1;
    int s = val ? __ldg(&g_ssrc[idx]) : 0;
#pragma unroll 4
    for (int base = e0; base < e1; base += 8) {
        int nidx = base + 8 + slot;
        bool nval = nidx < e1;
        int ns = nval ? __ldg(&g_ssrc[nidx]) : 0;   // prefetch next group
        float4 v = __ldg(&h4[s * 4 + cg]);
        if (val) {
            const __half2* hp = (const __half2*)&v;
            ADD_F32X2(A0, A0, pack_f2(__half22float2(hp[0])));
            ADD_F32X2(A1, A1, pack_f2(__half22float2(hp[1])));
            ADD_F32X2(A2, A2, pack_f2(__half22float2(hp[2])));
            ADD_F32X2(A3, A3, pack_f2(__half22float2(hp[3])));
        }
        s = ns; val = nval;
    }
    float2 f0 = unpack_f2(A0), f1 = unpack_f2(A1);
    float2 f2 = unpack_f2(A2), f3 = unpack_f2(A3);
    float a0 = f0.x, a1 = f0.y, a2 = f1.x, a3 = f1.y;
    float a4 = f2.x, a5 = f2.y, a6 = f3.x, a7 = f3.y;
    // reduce over edge-slots (lane bits 2,3,4)
#pragma unroll
    for (int ofs = 4; ofs <= 16; ofs <<= 1) {
        a0 += __shfl_xor_sync(0xffffffffu, a0, ofs);
        a1 += __shfl_xor_sync(0xffffffffu, a1, ofs);
        a2 += __shfl_xor_sync(0xffffffffu, a2, ofs);
        a3 += __shfl_xor_sync(0xffffffffu, a3, ofs);
        a4 += __shfl_xor_sync(0xffffffffu, a4, ofs);
        a5 += __shfl_xor_sync(0xffffffffu, a5, ofs);
        a6 += __shfl_xor_sync(0xffffffffu, a6, ofs);
        a7 += __shfl_xor_sync(0xffffffffu, a7, ofs);
    }
    if (lane < 4) {   // lane == cg, slot 0: owns columns cg*8 .. cg*8+7
        float invd = 1.0f / fmaxf((float)(e1 - e0), 1.0f);
        float4 bA = __ldg(&b1v[lane * 2 + 0]);
        float4 bB = __ldg(&b1v[lane * 2 + 1]);
        uint4 u;
        ((__half2*)&u)[0] = __floats2half2_rn(fmaxf(a0 * invd + bA.x, 0.f),
                                              fmaxf(a1 * invd + bA.y, 0.f));
        ((__half2*)&u)[1] = __floats2half2_rn(fmaxf(a2 * invd + bA.z, 0.f),
                                              fmaxf(a3 * invd + bA.w, 0.f));
        ((__half2*)&u)[2] = __floats2half2_rn(fmaxf(a4 * invd + bB.x, 0.f),
                                              fmaxf(a5 * invd + bB.y, 0.f));
        ((__half2*)&u)[3] = __floats2half2_rn(fmaxf(a6 * invd + bB.z, 0.f),
                                              fmaxf(a7 * invd + bB.w, 0.f));
        ((uint4*)g_xh)[w * 4 + lane] = u;   // 8 halves: cols cg*8..cg*8+7
    }
}

// ---------------------------------------------------------------------------
// h2 = x(fp16) @ W2   [NN,32] x [32,12], stored fp16 (24B rows)
__global__ __launch_bounds__(256) void gemm2_kernel(const float* __restrict__ W2) {
    __shared__ float W2s[HID * ODIM];
    int tid = threadIdx.x;
    for (int i = tid; i < HID * ODIM; i += 256) W2s[i] = W2[i];
    __syncthreads();

    int n = blockIdx.x * blockDim.x + tid;
    if (n >= NN) return;

    float acc[ODIM];
#pragma unroll
    for (int j = 0; j < ODIM; j++) acc[j] = 0.f;

    const uint4* x4 = (const uint4*)g_xh + (long long)n * 4;  // 4 x uint4 = 32 halves
#pragma unroll
    for (int q = 0; q < 4; q++) {
        uint4 u = x4[q];
        const __half2* hp = (const __half2*)&u;
#pragma unroll
        for (int p = 0; p < 4; p++) {
            float2 xv = __half22float2(hp[p]);
            int c = q * 8 + p * 2;
#pragma unroll
            for (int j = 0; j < ODIM; j++) {
                acc[j] += xv.x * W2s[(c + 0) * ODIM + j]
                        + xv.y * W2s[(c + 1) * ODIM + j];
            }
        }
    }
    uint2 u0, u1, u2;
    ((__half2*)&u0)[0] = __floats2half2_rn(acc[0], acc[1]);
    ((__half2*)&u0)[1] = __floats2half2_rn(acc[2], acc[3]);
    ((__half2*)&u1)[0] = __floats2half2_rn(acc[4], acc[5]);
    ((__half2*)&u1)[1] = __floats2half2_rn(acc[6], acc[7]);
    ((__half2*)&u2)[0] = __floats2half2_rn(acc[8], acc[9]);
    ((__half2*)&u2)[1] = __floats2half2_rn(acc[10], acc[11]);
    uint2* o = (uint2*)(g_h2h + (long long)n * ODIM);
    o[0] = u0; o[1] = u1; o[2] = u2;
}

// ---------------------------------------------------------------------------
// Gather 2 + finalize. Warp per node. fp16 rows (24B = 3x uint2).
// Index prefetch + packed f32x2 accumulation; 8 edges per LDG.64 warp-instr.
__global__ __launch_bounds__(256) void gather2_kernel(const float4* __restrict__ b2v,
                                                      float4* __restrict__ out4) {
    int w = (blockIdx.x * 256 + threadIdx.x) >> 5;
    int lane = threadIdx.x & 31;
    if (w >= NN) return;
    int e0 = __ldg(&g_rowstart[w]);
    int e1 = __ldg(&g_rowstart[w + 1]);

    int slot = lane >> 2;     // 0..7
    int cg   = lane & 3;      // 0..3 (3 idle)
    bool cact = cg < 3;
    const uint2* hp = (const uint2*)g_h2h;
    int coff = cact ? cg : 0;

    unsigned long long A0 = 0ull, A1 = 0ull;

    int idx = e0 + slot;
    bool val = idx < e1;
    int s = val ? __ldg(&g_ssrc[idx]) : 0;
#pragma unroll 4
    for (int base = e0; base < e1; base += 8) {
        int nidx = base + 8 + slot;
        bool nval = nidx < e1;
        int ns = nval ? __ldg(&g_ssrc[nidx]) : 0;
        uint2 d = __ldg(&hp[s * 3 + coff]);
        if (val && cact) {
            ADD_F32X2(A0, A0, pack_f2(__half22float2(*(const __half2*)&d.x)));
            ADD_F32X2(A1, A1, pack_f2(__half22float2(*(const __half2*)&d.y)));
        }
        s = ns; val = nval;
    }
    float2 f0 = unpack_f2(A0), f1 = unpack_f2(A1);
    float a0 = f0.x, a1 = f0.y, a2 = f1.x, a3 = f1.y;
#pragma unroll
    for (int ofs = 4; ofs <= 16; ofs <<= 1) {
        a0 += __shfl_xor_sync(0xffffffffu, a0, ofs);
        a1 += __shfl_xor_sync(0xffffffffu, a1, ofs);
        a2 += __shfl_xor_sync(0xffffffffu, a2, ofs);
        a3 += __shfl_xor_sync(0xffffffffu, a3, ofs);
    }
    if (lane < 3) {   // lane == cg: owns columns cg*4 .. cg*4+3
        float invd = 1.0f / fmaxf((float)(e1 - e0), 1.0f);
        float4 b = __ldg(&b2v[lane]);
        float4 o;
        o.x = fmaxf(a0 * invd + b.x, 0.f);
        o.y = fmaxf(a1 * invd + b.y, 0.f);
        o.z = fmaxf(a2 * invd + b.z, 0.f);
        o.w = fmaxf(a3 * invd + b.w, 0.f);
        out4[w * 3 + lane] = o;
    }
}

// ---------------------------------------------------------------------------
extern "C" void kernel_launch(void* const* d_in, const int* in_sizes, int n_in,
                              void* d_out, int out_size) {
    const float* feat = (const float*)d_in[0];  // [NN,128]
    const int*   src  = (const int*)d_in[1];    // [E]
    const int*   dst  = (const int*)d_in[2];    // [E]
    const float* W1   = (const float*)d_in[3];  // [128,32]
    const float* b1   = (const float*)d_in[4];  // [32]
    const float* W2   = (const float*)d_in[5];  // [32,12]
    const float* b2   = (const float*)d_in[6];  // [12]
    float* out = (float*)d_out;                 // [NN,12]

    int E = in_sizes[1];
    int E8 = E / 8;

    // Launch index 3 = permute (verify the 8-edge/thread MLP prediction)
    hist_kernel<<<(E8 + 255) / 256, 256>>>((const int4*)dst, E8, E, dst);      // 0
    scanA_kernel<<<NB_SCAN, 1024>>>();                                          // 1
    scanC_kernel<<<(NN + 255) / 256, 256>>>(E);                                 // 2
    permute_kernel<<<(E8 + 255) / 256, 256>>>((const int4*)src, (const int4*)dst,
                                              E8, E, src, dst);                 // 3
    gemm1_kernel<<<(NN + 63) / 64, 256>>>((const float4*)feat, W1);             // 4
    gather1_kernel<<<(NN * 32 + 255) / 256, 256>>>((const float4*)b1);          // 5
    gemm2_kernel<<<(NN + 255) / 256, 256>>>(W2);                                // 6
    gather2_kernel<<<(NN * 32 + 255) / 256, 256>>>((const float4*)b2,
                                                   (float4*)out);               // 7
}

// round 15
// speedup vs baseline: 1.6347x; 1.1534x over previous
#include <cuda_runtime.h>
#include <cuda_fp16.h>

#define NN 100000
#define IN_DIM 128
#define HID 32
#define ODIM 12
#define MAXE 3400000
#define SCAN_EPB 4096                              // elements per scanA block
#define NB_SCAN ((NN + SCAN_EPB - 1) / SCAN_EPB)   // 25

// Scratch (device globals; no allocation allowed). g_cnt relies on static
// zero-init for the first call; scanC re-zeroes it for every subsequent call.
__device__ __align__(128) __half g_h1h[NN * HID];    // feat @ W1  (fp16 at rest)
__device__ __align__(128) __half g_xh[NN * HID];     // layer-1 activations (fp16)
__device__ __align__(128) __half g_h2h[NN * ODIM];   // x @ W2     (fp16 at rest)
__device__ __align__(128) int    g_ssrc[MAXE];       // src sorted by dst
__device__ __align__(16) int g_cnt[NN];
__device__ __align__(16) int g_scanA[NN];            // exclusive-within-block
__device__ int g_rowstart[NN + 1];
__device__ int g_cursor[NN];
__device__ int g_bsum[32];

#define ADD_F32X2(out, a, b) \
    asm("add.rn.f32x2 %0, %1, %2;" : "=l"(out) : "l"(a), "l"(b))

__device__ __forceinline__ unsigned long long pack_f2(float2 f) {
    unsigned long long t;
    asm("mov.b64 %0, {%1, %2};" : "=l"(t) : "f"(f.x), "f"(f.y));
    return t;
}
__device__ __forceinline__ float2 unpack_f2(unsigned long long u) {
    float2 f;
    asm("mov.b64 {%0, %1}, %2;" : "=f"(f.x), "=f"(f.y) : "l"(u));
    return f;
}

// ---------------------------------------------------------------------------
// CSR build: degree histogram, 8 edges/thread.
__global__ void hist_kernel(const int4* __restrict__ dst4, int E8, int E,
                            const int* __restrict__ dst) {
    int i = blockIdx.x * blockDim.x + threadIdx.x;
    if (i < E8) {
        int4 d0 = dst4[2 * i];
        int4 d1 = dst4[2 * i + 1];
        atomicAdd(&g_cnt[d0.x], 1);
        atomicAdd(&g_cnt[d0.y], 1);
        atomicAdd(&g_cnt[d0.z], 1);
        atomicAdd(&g_cnt[d0.w], 1);
        atomicAdd(&g_cnt[d1.x], 1);
        atomicAdd(&g_cnt[d1.y], 1);
        atomicAdd(&g_cnt[d1.z], 1);
        atomicAdd(&g_cnt[d1.w], 1);
    }
    int tail = E8 * 8 + i;
    if (i < (E - E8 * 8)) atomicAdd(&g_cnt[dst[tail]], 1);
}

// Scan stage A: 4 elems/thread (int4), EXCLUSIVE-within-block output.
__global__ __launch_bounds__(1024) void scanA_kernel() {
    __shared__ int wsum[32];
    int tid = threadIdx.x, lane = tid & 31, wid = tid >> 5;
    int i4 = blockIdx.x * 1024 + tid;
    const int N4 = NN / 4;  // 25000
    int4 c = (i4 < N4) ? ((const int4*)g_cnt)[i4] : make_int4(0, 0, 0, 0);
    int l0 = c.x;
    int l1 = l0 + c.y;
    int l2 = l1 + c.z;
    int l3 = l2 + c.w;
    int x = l3;
#pragma unroll
    for (int o = 1; o < 32; o <<= 1) {
        int t = __shfl_up_sync(0xffffffffu, x, o);
        if (lane >= o) x += t;
    }
    if (lane == 31) wsum[wid] = x;
    __syncthreads();
    if (wid == 0) {
        int s = wsum[lane];
#pragma unroll
        for (int o = 1; o < 32; o <<= 1) {
            int t = __shfl_up_sync(0xffffffffu, s, o);
            if (lane >= o) s += t;
        }
        wsum[lane] = s;
    }
    __syncthreads();
    int add = (wid > 0 ? wsum[wid - 1] : 0) + (x - l3);  // exclusive of this thread
    if (i4 < N4) {
        int4 o;
        o.x = add; o.y = add + l0; o.z = add + l1; o.w = add + l2;
        ((int4*)g_scanA)[i4] = o;
    }
    if (tid == 1023) g_bsum[blockIdx.x] = wsum[31];
}

// Scan stage C (scanB inlined): every block shfl-scans the 25 block sums,
// then computes rowstart/cursor; also re-zeroes g_cnt for the next call.
__global__ __launch_bounds__(256) void scanC_kernel(int E) {
    __shared__ int boff[32];
    int tid = threadIdx.x;
    if (tid < 32) {
        int v = (tid < NB_SCAN) ? g_bsum[tid] : 0;
        int x = v;
#pragma unroll
        for (int o = 1; o < 32; o <<= 1) {
            int t = __shfl_up_sync(0xffffffffu, x, o);
            if (tid >= o) x += t;
        }
        boff[tid] = x - v;  // exclusive
    }
    __syncthreads();
    int n = blockIdx.x * 256 + tid;
    if (n < NN) {
        int rs = boff[n >> 12] + g_scanA[n];   // SCAN_EPB = 4096 = 1<<12
        g_rowstart[n] = rs;
        g_cursor[n] = rs;
        g_cnt[n] = 0;                          // clean for next call's hist
    }
    if (n == 0) g_rowstart[NN] = E;
}

// ---------------------------------------------------------------------------
// Permute: bucket src indices by dst (8 edges/thread; at its structural floor).
__global__ void permute_kernel(const int4* __restrict__ src4,
                               const int4* __restrict__ dst4, int E8, int E,
                               const int* __restrict__ src,
                               const int* __restrict__ dst) {
    int i = blockIdx.x * blockDim.x + threadIdx.x;
    if (i < E8) {
        int4 s0 = src4[2 * i],     s1 = src4[2 * i + 1];
        int4 d0 = dst4[2 * i],     d1 = dst4[2 * i + 1];
        int p0 = atomicAdd(&g_cursor[d0.x], 1);
        int p1 = atomicAdd(&g_cursor[d0.y], 1);
        int p2 = atomicAdd(&g_cursor[d0.z], 1);
        int p3 = atomicAdd(&g_cursor[d0.w], 1);
        int p4 = atomicAdd(&g_cursor[d1.x], 1);
        int p5 = atomicAdd(&g_cursor[d1.y], 1);
        int p6 = atomicAdd(&g_cursor[d1.z], 1);
        int p7 = atomicAdd(&g_cursor[d1.w], 1);
        g_ssrc[p0] = s0.x;
        g_ssrc[p1] = s0.y;
        g_ssrc[p2] = s0.z;
        g_ssrc[p3] = s0.w;
        g_ssrc[p4] = s1.x;
        g_ssrc[p5] = s1.y;
        g_ssrc[p6] = s1.z;
        g_ssrc[p7] = s1.w;
    }
    int tail = E8 * 8 + i;
    if (i < (E - E8 * 8))
        g_ssrc[atomicAdd(&g_cursor[dst[tail]], 1)] = src[tail];
}

// ---------------------------------------------------------------------------
// h1 = feat @ W1 via tensor cores (mma.sync.m16n8k16, fp16 in / fp32 acc).
// Block = 256 thr = 8 warps, 128 rows/block (16 rows/warp).
// A staged fp16 in smem, row stride 136 halves (272B): LDS.32 frag reads hit
// word (68g + t) mod 32 => all 32 banks, conflict-free. Fragments hand-packed
// (no ldmatrix) to eliminate layout risk:
//   a0=(A[g][2t],A[g][2t+1]) a1=(A[g+8][..]) a2/a3 = k+8 variants
//   b0=(B[2t][n],B[2t+1][n]) b1 = k+8, n = nt*8+g   (Wt stored [n][k])
//   c0=C[g][2t] c1=C[g][2t+1] c2/c3 = row g+8
__global__ __launch_bounds__(256) void gemm1_kernel(const float4* __restrict__ feat4,
                                                    const float* __restrict__ W1) {
    __shared__ __align__(16) __half As[128 * 136];   // 34.0 KB
    __shared__ __align__(16) __half Wt[32 * 136];    //  8.5 KB
    int tid = threadIdx.x;
    int base = blockIdx.x * 128;

    // Stage A: 128 rows x 32 float4, convert fp32->fp16
    for (int i = tid; i < 128 * 32; i += 256) {
        int row = i >> 5, c4 = i & 31;
        int g = base + row;
        float4 f = (g < NN) ? feat4[(long long)g * 32 + c4]
                            : make_float4(0.f, 0.f, 0.f, 0.f);
        uint2 u;
        ((__half2*)&u)[0] = __floats2half2_rn(f.x, f.y);
        ((__half2*)&u)[1] = __floats2half2_rn(f.z, f.w);
        *(uint2*)&As[row * 136 + c4 * 4] = u;
    }
    // Stage Wt[n][k] = W1[k][n] (transpose, fp16), k-pairs packed as half2
    {
        int n = tid >> 3, kg = tid & 7;
        int k0 = kg * 16;
#pragma unroll
        for (int kk = 0; kk < 16; kk += 2) {
            float w0 = W1[(k0 + kk) * HID + n];
            float w1 = W1[(k0 + kk + 1) * HID + n];
            *(__half2*)&Wt[n * 136 + k0 + kk] = __floats2half2_rn(w0, w1);
        }
    }
    __syncthreads();

    int warp = tid >> 5, lane = tid & 31;
    int g = lane >> 2, t2 = (lane & 3) * 2;
    int r0 = warp * 16;

    float c[4][4];
#pragma unroll
    for (int nt = 0; nt < 4; nt++)
#pragma unroll
        for (int j = 0; j < 4; j++) c[nt][j] = 0.f;

#pragma unroll
    for (int ks = 0; ks < 8; ks++) {
        int k0 = ks * 16;
        unsigned a0 = *(const unsigned*)&As[(r0 + g) * 136 + k0 + t2];
        unsigned a1 = *(const unsigned*)&As[(r0 + g + 8) * 136 + k0 + t2];
        unsigned a2 = *(const unsigned*)&As[(r0 + g) * 136 + k0 + t2 + 8];
        unsigned a3 = *(const unsigned*)&As[(r0 + g + 8) * 136 + k0 + t2 + 8];
#pragma unroll
        for (int nt = 0; nt < 4; nt++) {
            unsigned b0 = *(const unsigned*)&Wt[(nt * 8 + g) * 136 + k0 + t2];
            unsigned b1 = *(const unsigned*)&Wt[(nt * 8 + g) * 136 + k0 + t2 + 8];
            asm volatile(
                "mma.sync.aligned.m16n8k16.row.col.f32.f16.f16.f32 "
                "{%0,%1,%2,%3}, {%4,%5,%6,%7}, {%8,%9}, {%0,%1,%2,%3};"
                : "+f"(c[nt][0]), "+f"(c[nt][1]), "+f"(c[nt][2]), "+f"(c[nt][3])
                : "r"(a0), "r"(a1), "r"(a2), "r"(a3), "r"(b0), "r"(b1));
        }
    }

    int grow0 = base + r0 + g;
    int grow1 = grow0 + 8;
#pragma unroll
    for (int nt = 0; nt < 4; nt++) {
        if (grow0 < NN)
            *(__half2*)&g_h1h[(long long)grow0 * HID + nt * 8 + t2] =
                __floats2half2_rn(c[nt][0], c[nt][1]);
        if (grow1 < NN)
            *(__half2*)&g_h1h[(long long)grow1 * HID + nt * 8 + t2] =
                __floats2half2_rn(c[nt][2], c[nt][3]);
    }
}

// ---------------------------------------------------------------------------
// Gather 1 + finalize. Warp per node. Lane -> (edge-slot lane>>2, colgrp lane&3).
// Index prefetch + packed f32x2 accumulation. Output x stored fp16.
__global__ __launch_bounds__(256) void gather1_kernel(const float4* __restrict__ b1v) {
    int w = (blockIdx.x * 256 + threadIdx.x) >> 5;
    int lane = threadIdx.x & 31;
    if (w >= NN) return;
    int e0 = __ldg(&g_rowstart[w]);
    int e1 = __ldg(&g_rowstart[w + 1]);

    int slot = lane >> 2;     // 0..7 : edge within group of 8
    int cg   = lane & 3;      // 0..3 : which float4 (8 halves) of the 64B row
    const float4* h4 = (const float4*)g_h1h;

    unsigned long long A0 = 0ull, A1 = 0ull, A2 = 0ull, A3 = 0ull;

    int idx = e0 + slot;
    bool val = idx < e1;
    int s = val ? __ldg(&g_ssrc[idx]) : 0;
#pragma unroll 4
    for (int base = e0; base < e1; base += 8) {
        int nidx = base + 8 + slot;
        bool nval = nidx < e1;
        int ns = nval ? __ldg(&g_ssrc[nidx]) : 0;   // prefetch next group
        float4 v = __ldg(&h4[s * 4 + cg]);
        if (val) {
            const __half2* hp = (const __half2*)&v;
            ADD_F32X2(A0, A0, pack_f2(__half22float2(hp[0])));
            ADD_F32X2(A1, A1, pack_f2(__half22float2(hp[1])));
            ADD_F32X2(A2, A2, pack_f2(__half22float2(hp[2])));
            ADD_F32X2(A3, A3, pack_f2(__half22float2(hp[3])));
        }
        s = ns; val = nval;
    }
    float2 f0 = unpack_f2(A0), f1 = unpack_f2(A1);
    float2 f2 = unpack_f2(A2), f3 = unpack_f2(A3);
    float a0 = f0.x, a1 = f0.y, a2 = f1.x, a3 = f1.y;
    float a4 = f2.x, a5 = f2.y, a6 = f3.x, a7 = f3.y;
    // reduce over edge-slots (lane bits 2,3,4)
#pragma unroll
    for (int ofs = 4; ofs <= 16; ofs <<= 1) {
        a0 += __shfl_xor_sync(0xffffffffu, a0, ofs);
        a1 += __shfl_xor_sync(0xffffffffu, a1, ofs);
        a2 += __shfl_xor_sync(0xffffffffu, a2, ofs);
        a3 += __shfl_xor_sync(0xffffffffu, a3, ofs);
        a4 += __shfl_xor_sync(0xffffffffu, a4, ofs);
        a5 += __shfl_xor_sync(0xffffffffu, a5, ofs);
        a6 += __shfl_xor_sync(0xffffffffu, a6, ofs);
        a7 += __shfl_xor_sync(0xffffffffu, a7, ofs);
    }
    if (lane < 4) {   // lane == cg, slot 0: owns columns cg*8 .. cg*8+7
        float invd = 1.0f / fmaxf((float)(e1 - e0), 1.0f);
        float4 bA = __ldg(&b1v[lane * 2 + 0]);
        float4 bB = __ldg(&b1v[lane * 2 + 1]);
        uint4 u;
        ((__half2*)&u)[0] = __floats2half2_rn(fmaxf(a0 * invd + bA.x, 0.f),
                                              fmaxf(a1 * invd + bA.y, 0.f));
        ((__half2*)&u)[1] = __floats2half2_rn(fmaxf(a2 * invd + bA.z, 0.f),
                                              fmaxf(a3 * invd + bA.w, 0.f));
        ((__half2*)&u)[2] = __floats2half2_rn(fmaxf(a4 * invd + bB.x, 0.f),
                                              fmaxf(a5 * invd + bB.y, 0.f));
        ((__half2*)&u)[3] = __floats2half2_rn(fmaxf(a6 * invd + bB.z, 0.f),
                                              fmaxf(a7 * invd + bB.w, 0.f));
        ((uint4*)g_xh)[w * 4 + lane] = u;   // 8 halves: cols cg*8..cg*8+7
    }
}

// ---------------------------------------------------------------------------
// h2 = x(fp16) @ W2   [NN,32] x [32,12], stored fp16 (24B rows)
__global__ __launch_bounds__(256) void gemm2_kernel(const float* __restrict__ W2) {
    __shared__ float W2s[HID * ODIM];
    int tid = threadIdx.x;
    for (int i = tid; i < HID * ODIM; i += 256) W2s[i] = W2[i];
    __syncthreads();

    int n = blockIdx.x * blockDim.x + tid;
    if (n >= NN) return;

    float acc[ODIM];
#pragma unroll
    for (int j = 0; j < ODIM; j++) acc[j] = 0.f;

    const uint4* x4 = (const uint4*)g_xh + (long long)n * 4;  // 4 x uint4 = 32 halves
#pragma unroll
    for (int q = 0; q < 4; q++) {
        uint4 u = x4[q];
        const __half2* hp = (const __half2*)&u;
#pragma unroll
        for (int p = 0; p < 4; p++) {
            float2 xv = __half22float2(hp[p]);
            int c = q * 8 + p * 2;
#pragma unroll
            for (int j = 0; j < ODIM; j++) {
                acc[j] += xv.x * W2s[(c + 0) * ODIM + j]
                        + xv.y * W2s[(c + 1) * ODIM + j];
            }
        }
    }
    uint2 u0, u1, u2;
    ((__half2*)&u0)[0] = __floats2half2_rn(acc[0], acc[1]);
    ((__half2*)&u0)[1] = __floats2half2_rn(acc[2], acc[3]);
    ((__half2*)&u1)[0] = __floats2half2_rn(acc[4], acc[5]);
    ((__half2*)&u1)[1] = __floats2half2_rn(acc[6], acc[7]);
    ((__half2*)&u2)[0] = __floats2half2_rn(acc[8], acc[9]);
    ((__half2*)&u2)[1] = __floats2half2_rn(acc[10], acc[11]);
    uint2* o = (uint2*)(g_h2h + (long long)n * ODIM);
    o[0] = u0; o[1] = u1; o[2] = u2;
}

// ---------------------------------------------------------------------------
// Gather 2 + finalize. Warp per node. fp16 rows (24B = 3x uint2).
// Index prefetch + packed f32x2 accumulation; 8 edges per LDG.64 warp-instr.
__global__ __launch_bounds__(256) void gather2_kernel(const float4* __restrict__ b2v,
                                                      float4* __restrict__ out4) {
    int w = (blockIdx.x * 256 + threadIdx.x) >> 5;
    int lane = threadIdx.x & 31;
    if (w >= NN) return;
    int e0 = __ldg(&g_rowstart[w]);
    int e1 = __ldg(&g_rowstart[w + 1]);

    int slot = lane >> 2;     // 0..7
    int cg   = lane & 3;      // 0..3 (3 idle)
    bool cact = cg < 3;
    const uint2* hp = (const uint2*)g_h2h;
    int coff = cact ? cg : 0;

    unsigned long long A0 = 0ull, A1 = 0ull;

    int idx = e0 + slot;
    bool val = idx < e1;
    int s = val ? __ldg(&g_ssrc[idx]) : 0;
#pragma unroll 4
    for (int base = e0; base < e1; base += 8) {
        int nidx = base + 8 + slot;
        bool nval = nidx < e1;
        int ns = nval ? __ldg(&g_ssrc[nidx]) : 0;
        uint2 d = __ldg(&hp[s * 3 + coff]);
        if (val && cact) {
            ADD_F32X2(A0, A0, pack_f2(__half22float2(*(const __half2*)&d.x)));
            ADD_F32X2(A1, A1, pack_f2(__half22float2(*(const __half2*)&d.y)));
        }
        s = ns; val = nval;
    }
    float2 f0 = unpack_f2(A0), f1 = unpack_f2(A1);
    float a0 = f0.x, a1 = f0.y, a2 = f1.x, a3 = f1.y;
#pragma unroll
    for (int ofs = 4; ofs <= 16; ofs <<= 1) {
        a0 += __shfl_xor_sync(0xffffffffu, a0, ofs);
        a1 += __shfl_xor_sync(0xffffffffu, a1, ofs);
        a2 += __shfl_xor_sync(0xffffffffu, a2, ofs);
        a3 += __shfl_xor_sync(0xffffffffu, a3, ofs);
    }
    if (lane < 3) {   // lane == cg: owns columns cg*4 .. cg*4+3
        float invd = 1.0f / fmaxf((float)(e1 - e0), 1.0f);
        float4 b = __ldg(&b2v[lane]);
        float4 o;
        o.x = fmaxf(a0 * invd + b.x, 0.f);
        o.y = fmaxf(a1 * invd + b.y, 0.f);
        o.z = fmaxf(a2 * invd + b.z, 0.f);
        o.w = fmaxf(a3 * invd + b.w, 0.f);
        out4[w * 3 + lane] = o;
    }
}

// ---------------------------------------------------------------------------
extern "C" void kernel_launch(void* const* d_in, const int* in_sizes, int n_in,
                              void* d_out, int out_size) {
    const float* feat = (const float*)d_in[0];  // [NN,128]
    const int*   src  = (const int*)d_in[1];    // [E]
    const int*   dst  = (const int*)d_in[2];    // [E]
    const float* W1   = (const float*)d_in[3];  // [128,32]
    const float* b1   = (const float*)d_in[4];  // [32]
    const float* W2   = (const float*)d_in[5];  // [32,12]
    const float* b2   = (const float*)d_in[6];  // [12]
    float* out = (float*)d_out;                 // [NN,12]

    int E = in_sizes[1];
    int E8 = E / 8;

    // Launch index 3 = gemm1 (verify the HMMA rewrite with ncu)
    hist_kernel<<<(E8 + 255) / 256, 256>>>((const int4*)dst, E8, E, dst);      // 0
    scanA_kernel<<<NB_SCAN, 1024>>>();                                          // 1
    scanC_kernel<<<(NN + 255) / 256, 256>>>(E);                                 // 2
    gemm1_kernel<<<(NN + 127) / 128, 256>>>((const float4*)feat, W1);           // 3
    permute_kernel<<<(E8 + 255) / 256, 256>>>((const int4*)src, (const int4*)dst,
                                              E8, E, src, dst);                 // 4
    gather1_kernel<<<(NN * 32 + 255) / 256, 256>>>((const float4*)b1);          // 5
    gemm2_kernel<<<(NN + 255) / 256, 256>>>(W2);                                // 6
    gather2_kernel<<<(NN * 32 + 255) / 256, 256>>>((const float4*)b2,
                                                   (float4*)out);               // 7
}